// round 14
// baseline (speedup 1.0000x reference)
#include <cuda_runtime.h>
#include <cstdint>

#define BB 16
#define TT 32
#define FF 8
#define SS 256
#define HH 512
#define KX 520         // F + H
#define GRID 128
#define NTH 512

// ---------------- smem layout (floats) ----------------
#define OFF_XP   0          // 16 x 520 packed batch-pairs (8320)
#define OFF_HP   8320       // 16 x 512 packed (8192)
#define OFF_EX   16512      // 768 exchange
#define OFF_W0I  17280      // 12 x 520 (6240)
#define OFF_W0H  23520      // 12 x 512 (6144)
#define OFF_W1I  29664      // 12 x 512 (6144)
#define OFF_W1H  35808      // 12 x 512 (6144)
#define OFF_WT   41952      // 8 x 1024 attnW rows (8192)
#define OFF_VW   50144      // 512
#define SMEM_FLOATS 50656   // 202624 bytes

// ---------------- device scratch (static, no allocation) ----------------
__device__ float g_encW2[BB * SS * HH];   // 8 MB, enc @ W2^T (step-invariant)
__device__ float g_hW1[BB * HH];
__device__ float g_scores[BB * SS];       // holds exp(score)
__device__ float g_weighted[BB * HH];
__device__ float g_xin[BB * FF];
__device__ float g_h0[2][BB * HH];
__device__ float g_h1[2][BB * HH];
__device__ int   g_bar_count;             // self-resetting
__device__ int   g_gen;                   // monotonic across replays

// ---------------- helpers ----------------
__device__ __forceinline__ float2 ffma2(float2 a, float2 b, float2 c) {
    unsigned long long A = *reinterpret_cast<unsigned long long*>(&a);
    unsigned long long Bv = *reinterpret_cast<unsigned long long*>(&b);
    unsigned long long C = *reinterpret_cast<unsigned long long*>(&c);
    unsigned long long D;
    asm("fma.rn.f32x2 %0, %1, %2, %3;" : "=l"(D) : "l"(A), "l"(Bv), "l"(C));
    return *reinterpret_cast<float2*>(&D);
}
__device__ __forceinline__ float htanh(float x) {
    float y; asm("tanh.approx.f32 %0, %1;" : "=f"(y) : "f"(x)); return y;
}
__device__ __forceinline__ float hsig(float x) {
    return fmaf(htanh(0.5f * x), 0.5f, 0.5f);
}
__device__ __forceinline__ float  lcg(const float* p)  { return __ldcg(p); }
__device__ __forceinline__ float2 lcg2(const float* p) { return __ldcg(reinterpret_cast<const float2*>(p)); }

// Flat grid barrier. No gpu-scope fences (CCTL.IVALL would flush L1D);
// mutable cross-block data is always read via .cg (L2) instead.
__device__ __forceinline__ void gridbar() {
    __syncthreads();
    if (threadIdx.x == 0) {
        int gen;
        asm volatile("ld.relaxed.gpu.s32 %0, [%1];" : "=r"(gen) : "l"(&g_gen) : "memory");
        int prev;
        asm volatile("atom.release.gpu.add.s32 %0, [%1], %2;"
                     : "=r"(prev) : "l"(&g_bar_count), "r"(1) : "memory");
        if (prev == GRID - 1) {
            asm volatile("st.relaxed.gpu.s32 [%0], %1;" :: "l"(&g_bar_count), "r"(0) : "memory");
            asm volatile("st.release.gpu.s32 [%0], %1;" :: "l"(&g_gen), "r"(gen + 1) : "memory");
        } else {
            int cur;
            do {
                asm volatile("ld.acquire.gpu.s32 %0, [%1];" : "=r"(cur) : "l"(&g_gen) : "memory");
            } while (cur == gen);
        }
    }
    __syncthreads();
}

// ---------------- encW2 = enc @ W2^T  (prologue GEMM) ----------------
__global__ void __launch_bounds__(256) kEncW2(const float* __restrict__ enc,
                                              const float* __restrict__ attnW) {
    __shared__ float As[32][68];
    __shared__ float Bs[32][72];
    int Mblk = blockIdx.y * 64;
    int Nblk = blockIdx.x * 64;
    int tid = threadIdx.x;
    int tx = tid & 15, ty = tid >> 4;

    float2 acc[4][2];
#pragma unroll
    for (int i = 0; i < 4; i++) { acc[i][0] = make_float2(0.f, 0.f); acc[i][1] = make_float2(0.f, 0.f); }

    const float* Ag = enc + (size_t)Mblk * 512;
    const float* Bg = attnW + (size_t)Nblk * 1024 + 512;

    for (int k0 = 0; k0 < 512; k0 += 32) {
#pragma unroll
        for (int r = 0; r < 2; r++) {
            int i = r * 256 + tid;
            int m = i >> 3, g = i & 7;
            float4 v = *reinterpret_cast<const float4*>(Ag + m * 512 + k0 + g * 4);
            As[g * 4 + 0][m] = v.x; As[g * 4 + 1][m] = v.y;
            As[g * 4 + 2][m] = v.z; As[g * 4 + 3][m] = v.w;
            float4 u = *reinterpret_cast<const float4*>(Bg + m * 1024 + k0 + g * 4);
            Bs[g * 4 + 0][m] = u.x; Bs[g * 4 + 1][m] = u.y;
            Bs[g * 4 + 2][m] = u.z; Bs[g * 4 + 3][m] = u.w;
        }
        __syncthreads();
#pragma unroll
        for (int kk = 0; kk < 32; kk++) {
            float4 a4 = *reinterpret_cast<const float4*>(&As[kk][ty * 4]);
            float2 b0 = *reinterpret_cast<const float2*>(&Bs[kk][tx * 4]);
            float2 b1 = *reinterpret_cast<const float2*>(&Bs[kk][tx * 4 + 2]);
            float2 aa;
            aa.x = aa.y = a4.x; acc[0][0] = ffma2(aa, b0, acc[0][0]); acc[0][1] = ffma2(aa, b1, acc[0][1]);
            aa.x = aa.y = a4.y; acc[1][0] = ffma2(aa, b0, acc[1][0]); acc[1][1] = ffma2(aa, b1, acc[1][1]);
            aa.x = aa.y = a4.z; acc[2][0] = ffma2(aa, b0, acc[2][0]); acc[2][1] = ffma2(aa, b1, acc[2][1]);
            aa.x = aa.y = a4.w; acc[3][0] = ffma2(aa, b0, acc[3][0]); acc[3][1] = ffma2(aa, b1, acc[3][1]);
        }
        __syncthreads();
    }
#pragma unroll
    for (int i = 0; i < 4; i++) {
        float* row = g_encW2 + (size_t)(Mblk + ty * 4 + i) * 512 + Nblk + tx * 4;
        *reinterpret_cast<float2*>(row) = acc[i][0];
        *reinterpret_cast<float2*>(row + 2) = acc[i][1];
    }
}

// ================== persistent-kernel phases ==================

// scores: warp per (b,s); exactly 2 pairs per warp (4096 / 2048 warps)
__device__ __forceinline__ void scores_phase(const float* __restrict__ smvw) {
    int tid = threadIdx.x, w = tid >> 5, l = tid & 31;
#pragma unroll
    for (int it = 0; it < 2; it++) {
        int pr = blockIdx.x * 16 + w + it * 2048;
        int b = pr >> 8;
        const float* e = g_encW2 + (size_t)pr * HH;
        const float* hr = g_hW1 + b * HH;
        float acc = 0.f;
#pragma unroll
        for (int i = 0; i < 16; i++) {
            int k = l + 32 * i;
            acc += htanh(e[k] + lcg(hr + k)) * smvw[k];
        }
#pragma unroll
        for (int off = 16; off > 0; off >>= 1) acc += __shfl_xor_sync(0xffffffffu, acc, off);
        if (l == 0) g_scores[pr] = __expf(acc);
    }
}

// weighted sum: block = (b, 64-h chunk); scores already exp'ed
__device__ __forceinline__ void weighted_phase(float* sm, const float* __restrict__ enc) {
    int bi = blockIdx.x;
    int tid = threadIdx.x;
    int b = bi >> 3, hc = bi & 7;
    float* wsm  = sm + OFF_XP;        // 256 raw exps
    float* red  = sm + OFF_XP + 256;  // 512
    float* wred = sm + OFF_XP + 768;  // 16

    float e = (tid < 256) ? lcg(&g_scores[b * SS + tid]) : 0.f;
    if (tid < 256) wsm[tid] = e;
    float s = e;
#pragma unroll
    for (int off = 16; off > 0; off >>= 1) s += __shfl_xor_sync(0xffffffffu, s, off);
    if ((tid & 31) == 0) wred[tid >> 5] = s;
    __syncthreads();
    float tot = 0.f;
#pragma unroll
    for (int i = 0; i < 16; i++) tot += wred[i];
    float inv = __fdividef(1.f, tot);

    int h = hc * 64 + (tid & 63), sg = tid >> 6;
    const float* ep = enc + (size_t)b * SS * HH + h;
    float acc = 0.f;
#pragma unroll
    for (int s2 = 0; s2 < 32; s2++) {
        int si = sg + s2 * 8;
        acc += wsm[si] * ep[(size_t)si * HH];
    }
    red[tid] = acc;
    __syncthreads();
    if (tid < 64) {
        float v = 0.f;
#pragma unroll
        for (int g = 0; g < 8; g++) v += red[tid + 64 * g];
        g_weighted[b * HH + hc * 64 + tid] = v * inv;
    }
}

// GRU layer: 128 blocks x 4 j; 16 warps = {gi,gh} x {4 j} x {2 K-halves}
// Weights are SMEM-resident (loaded once). Layer0 x layout: [weighted(512), xin(8)].
template <int LAYER>
__device__ __forceinline__ void gru_phase(float* sm, int p,
                                          const float* __restrict__ bih,
                                          const float* __restrict__ bhh) {
    int bi = blockIdx.x;
    int tid = threadIdx.x;
    constexpr int K = (LAYER == 0) ? KX : HH;
    float* xp = sm + OFF_XP;
    float* hp = sm + OFF_HP;
    float* ex = sm + OFF_EX;

    const float* hold = (LAYER == 0) ? g_h0[p] : g_h1[p];
    float* hnew       = (LAYER == 0) ? g_h0[1 - p] : g_h1[1 - p];

    if (LAYER == 0) {
#pragma unroll
        for (int r = 0; r < 16; r++) {
            int i = r * NTH + tid;
            int b = i >> 9, k = i & 511;
            xp[(b >> 1) * (2 * K) + 2 * k + (b & 1)] = lcg(g_weighted + b * HH + k);
        }
        if (tid < 128) {
            int b = tid >> 3, f = tid & 7;
            xp[(b >> 1) * (2 * K) + 2 * (512 + f) + (b & 1)] = lcg(g_xin + b * FF + f);
        }
    } else {
        const float* src0 = g_h0[1 - p];
#pragma unroll
        for (int r = 0; r < 16; r++) {
            int i = r * NTH + tid;
            int b = i >> 9, k = i & 511;
            xp[(b >> 1) * 1024 + 2 * k + (b & 1)] = lcg(src0 + b * HH + k);
        }
    }
#pragma unroll
    for (int r = 0; r < 16; r++) {
        int i = r * NTH + tid;
        int b = i >> 9, k = i & 511;
        hp[(b >> 1) * 1024 + 2 * k + (b & 1)] = lcg(hold + b * HH + k);
    }
    __syncthreads();

    int w = tid >> 5, l = tid & 31;
    int jrel = w & 3;
    int role = (w >> 2) & 1;       // 0 = gi, 1 = gh
    int kh = w >> 3;

    float2 a0[8], a1[8], a2[8];
#pragma unroll
    for (int bp = 0; bp < 8; bp++) { a0[bp] = make_float2(0.f, 0.f); a1[bp] = a0[bp]; a2[bp] = a0[bp]; }

    int k0 = l + kh * 32;
    if (role == 0) {
        const float2* src = reinterpret_cast<const float2*>(xp);
        const float* wbase = sm + ((LAYER == 0) ? OFF_W0I : OFF_W1I);
        constexpr int WR = (LAYER == 0) ? 520 : 512;
        const float* wr = wbase + jrel * WR;
        const float* wz = wbase + (4 + jrel) * WR;
        const float* wn = wbase + (8 + jrel) * WR;
#pragma unroll
        for (int ii = 0; ii < 8; ii++) {
            int k = k0 + ii * 64;
            float r_ = wr[k], z_ = wz[k], n_ = wn[k];
            float2 rr = make_float2(r_, r_), zz = make_float2(z_, z_), nn = make_float2(n_, n_);
#pragma unroll
            for (int bp = 0; bp < 8; bp++) {
                float2 x2 = src[bp * K + k];
                a0[bp] = ffma2(x2, rr, a0[bp]);
                a1[bp] = ffma2(x2, zz, a1[bp]);
                a2[bp] = ffma2(x2, nn, a2[bp]);
            }
        }
        if (LAYER == 0 && kh == 0 && l < FF) {
            int k = 512 + l;
            float r_ = wr[k], z_ = wz[k], n_ = wn[k];
            float2 rr = make_float2(r_, r_), zz = make_float2(z_, z_), nn = make_float2(n_, n_);
#pragma unroll
            for (int bp = 0; bp < 8; bp++) {
                float2 x2 = src[bp * K + k];
                a0[bp] = ffma2(x2, rr, a0[bp]);
                a1[bp] = ffma2(x2, zz, a1[bp]);
                a2[bp] = ffma2(x2, nn, a2[bp]);
            }
        }
    } else {
        const float2* src = reinterpret_cast<const float2*>(hp);
        const float* wbase = sm + ((LAYER == 0) ? OFF_W0H : OFF_W1H);
        const float* wr = wbase + jrel * 512;
        const float* wz = wbase + (4 + jrel) * 512;
        const float* wn = wbase + (8 + jrel) * 512;
#pragma unroll
        for (int ii = 0; ii < 8; ii++) {
            int k = k0 + ii * 64;
            float r_ = wr[k], z_ = wz[k], n_ = wn[k];
            float2 rr = make_float2(r_, r_), zz = make_float2(z_, z_), nn = make_float2(n_, n_);
#pragma unroll
            for (int bp = 0; bp < 8; bp++) {
                float2 x2 = src[bp * 512 + k];
                a0[bp] = ffma2(x2, rr, a0[bp]);
                a1[bp] = ffma2(x2, zz, a1[bp]);
                a2[bp] = ffma2(x2, nn, a2[bp]);
            }
        }
    }
#pragma unroll
    for (int off = 16; off > 0; off >>= 1) {
#pragma unroll
        for (int bp = 0; bp < 8; bp++) {
            a0[bp].x += __shfl_xor_sync(0xffffffffu, a0[bp].x, off);
            a0[bp].y += __shfl_xor_sync(0xffffffffu, a0[bp].y, off);
            a1[bp].x += __shfl_xor_sync(0xffffffffu, a1[bp].x, off);
            a1[bp].y += __shfl_xor_sync(0xffffffffu, a1[bp].y, off);
            a2[bp].x += __shfl_xor_sync(0xffffffffu, a2[bp].x, off);
            a2[bp].y += __shfl_xor_sync(0xffffffffu, a2[bp].y, off);
        }
    }
    if (l == 0) {
        float* dst = ex + ((role * 2 + kh) * 4 + jrel) * 48;
#pragma unroll
        for (int bp = 0; bp < 8; bp++) {
            dst[2 * bp] = a0[bp].x;      dst[2 * bp + 1] = a0[bp].y;
            dst[16 + 2 * bp] = a1[bp].x; dst[16 + 2 * bp + 1] = a1[bp].y;
            dst[32 + 2 * bp] = a2[bp].x; dst[32 + 2 * bp + 1] = a2[bp].y;
        }
    }
    __syncthreads();
    if (tid < 64) {
        int b = tid & 15, jr = tid >> 4;
        int jj = bi * 4 + jr;
        const float* gi0 = ex + (0 * 4 + jr) * 48;
        const float* gi1 = ex + (1 * 4 + jr) * 48;
        const float* gh0 = ex + (2 * 4 + jr) * 48;
        const float* gh1 = ex + (3 * 4 + jr) * 48;
        float gir = gi0[b] + gi1[b], giz = gi0[16 + b] + gi1[16 + b], gin = gi0[32 + b] + gi1[32 + b];
        float ghr = gh0[b] + gh1[b], ghz = gh0[16 + b] + gh1[16 + b], ghn = gh0[32 + b] + gh1[32 + b];
        float r = hsig(gir + bih[jj] + ghr + bhh[jj]);
        float z = hsig(giz + bih[jj + 512] + ghz + bhh[jj + 512]);
        float n = htanh(gin + bih[jj + 1024] + r * (ghn + bhh[jj + 1024]));
        float hprev = hp[(b >> 1) * 1024 + 2 * jj + (b & 1)];
        hnew[b * HH + jj] = (1.f - z) * n + z * hprev;
    }
}

// tail: blocks 0..63 compute next-step hW1 (weights in smem); block 64 out-proj
__device__ __forceinline__ void tail_phase(float* sm, int pn, int t,
                                           const float* __restrict__ attnb,
                                           const float* __restrict__ outW,
                                           const float* __restrict__ outb,
                                           float* __restrict__ dout) {
    int bi = blockIdx.x;
    int tid = threadIdx.x;
    const float* h1 = g_h1[pn];

    if (bi < 64) {
        float* hp = sm + OFF_HP;
        float* ex = sm + OFF_EX;
#pragma unroll
        for (int r = 0; r < 16; r++) {
            int i = r * NTH + tid;
            int b = i >> 9, k = i & 511;
            hp[(b >> 1) * 1024 + 2 * k + (b & 1)] = lcg(h1 + b * HH + k);
        }
        __syncthreads();
        int w = tid >> 5, l = tid & 31;
        int jrel = w & 7, kh = w >> 3;
        const float2* hp2 = reinterpret_cast<const float2*>(hp);
        const float* wcol = sm + OFF_WT + jrel * 1024;
        float2 acc[8];
#pragma unroll
        for (int bp = 0; bp < 8; bp++) acc[bp] = make_float2(0.f, 0.f);
        int k0 = l + kh * 32;
#pragma unroll
        for (int ii = 0; ii < 8; ii++) {
            int k = k0 + ii * 64;
            float wv = wcol[k];
            float2 ww = make_float2(wv, wv);
#pragma unroll
            for (int bp = 0; bp < 8; bp++) acc[bp] = ffma2(hp2[bp * 512 + k], ww, acc[bp]);
        }
#pragma unroll
        for (int off = 16; off > 0; off >>= 1) {
#pragma unroll
            for (int bp = 0; bp < 8; bp++) {
                acc[bp].x += __shfl_xor_sync(0xffffffffu, acc[bp].x, off);
                acc[bp].y += __shfl_xor_sync(0xffffffffu, acc[bp].y, off);
            }
        }
        if (l == 0) {
            float* dst = ex + (kh * 8 + jrel) * 16;
#pragma unroll
            for (int bp = 0; bp < 8; bp++) { dst[2 * bp] = acc[bp].x; dst[2 * bp + 1] = acc[bp].y; }
        }
        __syncthreads();
        if (tid < 128) {
            int b = tid & 15, jr = tid >> 4;
            int jj = bi * 8 + jr;
            g_hW1[b * HH + jj] = ex[jr * 16 + b] + ex[(8 + jr) * 16 + b] + attnb[jj];
        }
    } else if (bi == 64 && t >= 0) {
        float* red = sm + OFF_XP;
        int out = tid & 127, kc = tid >> 7;
        int b = out >> 3, f = out & 7;
        const float* wrow = outW + f * (2 * HH + FF);
        float acc = 0.f;
        if (kc < 2) {
            const float2* w2 = reinterpret_cast<const float2*>(wrow + kc * 256);
            const float* h2 = h1 + b * HH + kc * 256;
#pragma unroll
            for (int c = 0; c < 128; c++) {
                float2 wv = w2[c]; float2 hv = lcg2(h2 + 2 * c);
                acc += wv.x * hv.x + wv.y * hv.y;
            }
        } else {
            const float2* w2 = reinterpret_cast<const float2*>(wrow + 512 + (kc - 2) * 256);
            const float* g2 = g_weighted + b * HH + (kc - 2) * 256;
#pragma unroll
            for (int c = 0; c < 128; c++) {
                float2 wv = w2[c]; float2 gv = lcg2(g2 + 2 * c);
                acc += wv.x * gv.x + wv.y * gv.y;
            }
            if (kc == 3) {
#pragma unroll
                for (int c = 0; c < FF; c++) acc += wrow[2 * HH + c] * lcg(&g_xin[b * FF + c]);
                acc += outb[f];
            }
        }
        red[tid] = acc;
        __syncthreads();
        if (kc == 0) {
            float v = red[out] + red[out + 128] + red[out + 256] + red[out + 384];
            v = fmaxf(v, 0.f);
            dout[(b * TT + t) * FF + f] = v;
            g_xin[out] = v;   // next_in = out (TGT_IDX covers all F)
        }
    }
}

// ================== persistent kernel ==================
__global__ void __launch_bounds__(NTH, 1)
kPersist(const float* __restrict__ target, const float* __restrict__ hidden0,
         const float* __restrict__ enc, const float* __restrict__ attnW,
         const float* __restrict__ attnb, const float* __restrict__ v_w,
         const float* __restrict__ Wih0, const float* __restrict__ Whh0,
         const float* __restrict__ bih0, const float* __restrict__ bhh0,
         const float* __restrict__ Wih1, const float* __restrict__ Whh1,
         const float* __restrict__ bih1, const float* __restrict__ bhh1,
         const float* __restrict__ outW, const float* __restrict__ outb,
         float* __restrict__ dout)
{
    extern __shared__ float sm[];
    int tid = threadIdx.x, bi = blockIdx.x;

    // ---- one-time: load step-invariant weights into smem ----
    // Wih0 rows (gate g, jrel) with column remap: smem col c<512 -> global c+8 (weighted),
    // c>=512 -> global c-512 (xin); matches xp layout [weighted, xin].
    for (int i = tid; i < 12 * 520; i += NTH) {
        int r = i / 520, c = i - r * 520;
        int g = r >> 2, jr = r & 3;
        int gc = (c < 512) ? (c + 8) : (c - 512);
        sm[OFF_W0I + i] = Wih0[(size_t)(g * 512 + bi * 4 + jr) * 520 + gc];
    }
#pragma unroll
    for (int r = 0; r < 12; r++) {
        int g = r >> 2, jr = r & 3;
        size_t grow = (size_t)(g * 512 + bi * 4 + jr) * 512;
        for (int c = tid; c < 512; c += NTH) {
            sm[OFF_W0H + r * 512 + c] = Whh0[grow + c];
            sm[OFF_W1I + r * 512 + c] = Wih1[grow + c];
            sm[OFF_W1H + r * 512 + c] = Whh1[grow + c];
        }
    }
    if (bi < 64) {
        for (int i = tid; i < 8 * 1024; i += NTH) {
            int r = i >> 10, c = i & 1023;
            sm[OFF_WT + i] = attnW[(size_t)(bi * 8 + r) * 1024 + c];
        }
    }
    for (int i = tid; i < 512; i += NTH) sm[OFF_VW + i] = v_w[i];

    // ---- init state ----
    for (int i = bi * NTH + tid; i < BB * HH; i += GRID * NTH) {
        g_h0[0][i] = hidden0[i];
        g_h1[0][i] = hidden0[BB * HH + i];
    }
    if (bi == 0 && tid < BB * FF) {
        int b = tid >> 3, f = tid & 7;
        g_xin[tid] = target[b * TT * FF + f];
    }
    __syncthreads();
    gridbar();

    tail_phase(sm, 0, -1, attnb, outW, outb, dout);
    gridbar();

    for (int t = 0; t < TT; t++) {
        int p = t & 1, pn = 1 - p;
        scores_phase(sm + OFF_VW);
        gridbar();
        weighted_phase(sm, enc);
        gridbar();
        gru_phase<0>(sm, p, bih0, bhh0);
        gridbar();
        gru_phase<1>(sm, p, bih1, bhh1);
        gridbar();
        tail_phase(sm, pn, t, attnb, outW, outb, dout);
        gridbar();
    }
}

// ---------------- launch ----------------
extern "C" void kernel_launch(void* const* d_in, const int* in_sizes, int n_in,
                              void* d_out, int out_size) {
    (void)in_sizes; (void)n_in; (void)out_size;
    const float* target  = (const float*)d_in[0];
    const float* hidden0 = (const float*)d_in[1];
    const float* enc     = (const float*)d_in[2];
    const float* attnW   = (const float*)d_in[3];
    const float* attnb   = (const float*)d_in[4];
    const float* v_w     = (const float*)d_in[5];
    const float* Wih0    = (const float*)d_in[6];
    const float* Whh0    = (const float*)d_in[7];
    const float* bih0    = (const float*)d_in[8];
    const float* bhh0    = (const float*)d_in[9];
    const float* Wih1    = (const float*)d_in[10];
    const float* Whh1    = (const float*)d_in[11];
    const float* bih1    = (const float*)d_in[12];
    const float* bhh1    = (const float*)d_in[13];
    const float* outW    = (const float*)d_in[14];
    const float* outb    = (const float*)d_in[15];
    float* dout = (float*)d_out;

    const int smem = SMEM_FLOATS * 4;  // 202624 B
    static int cfg_done = 0;
    if (!cfg_done) {
        cudaFuncSetAttribute(kPersist, cudaFuncAttributeMaxDynamicSharedMemorySize, smem);
        cfg_done = 1;
    }

    kEncW2<<<dim3(8, 64), 256>>>(enc, attnW);
    kPersist<<<GRID, NTH, smem>>>(target, hidden0, enc, attnW, attnb, v_w,
                                  Wih0, Whh0, bih0, bhh0,
                                  Wih1, Whh1, bih1, bhh1,
                                  outW, outb, dout);
}

// round 17
// speedup vs baseline: 1.1481x; 1.1481x over previous
#include <cuda_runtime.h>
#include <cuda_fp16.h>
#include <cstdint>

#define BB 16
#define TT 32
#define FF 8
#define SS 256
#define HH 512
#define KX 520         // F + H
#define GRID 129
#define NTH 512

// smem layout (floats)
#define OFF_XP 0        // 16x520 packed batch-pairs (8320)
#define OFF_HP 8320     // 16x512 packed (8192)
#define OFF_EX 16512    // 384 exchange
#define SMEM_FLOATS 16896

// ---------------- device scratch (static, no allocation) ----------------
__device__ __half g_encW2h[BB * SS * HH];  // 4 MB, fp16 enc@W2^T (step-invariant)
__device__ __half g_ench[BB * SS * HH];    // 4 MB, fp16 copy of enc
__device__ float g_hW1[BB * HH];
__device__ float g_scores[BB * SS];        // exp(score)
__device__ float g_weighted[BB * HH];
__device__ float g_xin[BB * FF];
__device__ float g_h0[2][BB * HH];
__device__ float g_h1[2][BB * HH];
__device__ int   g_bar_count;              // self-resetting
__device__ int   g_gen;                    // monotonic across replays

// ---------------- helpers ----------------
__device__ __forceinline__ float2 ffma2(float2 a, float2 b, float2 c) {
    unsigned long long A = *reinterpret_cast<unsigned long long*>(&a);
    unsigned long long Bv = *reinterpret_cast<unsigned long long*>(&b);
    unsigned long long C = *reinterpret_cast<unsigned long long*>(&c);
    unsigned long long D;
    asm("fma.rn.f32x2 %0, %1, %2, %3;" : "=l"(D) : "l"(A), "l"(Bv), "l"(C));
    return *reinterpret_cast<float2*>(&D);
}
__device__ __forceinline__ float htanh(float x) {
    float y; asm("tanh.approx.f32 %0, %1;" : "=f"(y) : "f"(x)); return y;
}
__device__ __forceinline__ float hsig(float x) {
    return fmaf(htanh(0.5f * x), 0.5f, 0.5f);
}
__device__ __forceinline__ float  lcg(const float* p)  { return __ldcg(p); }
__device__ __forceinline__ float2 lcg2(const float* p) { return __ldcg(reinterpret_cast<const float2*>(p)); }

// Flat grid barrier; no gpu-scope fences (CCTL.IVALL would flush L1D).
// Mutable cross-block data is always read via .cg (L2).
__device__ __forceinline__ void gridbar() {
    __syncthreads();
    if (threadIdx.x == 0) {
        int gen;
        asm volatile("ld.relaxed.gpu.s32 %0, [%1];" : "=r"(gen) : "l"(&g_gen) : "memory");
        int prev;
        asm volatile("atom.release.gpu.add.s32 %0, [%1], %2;"
                     : "=r"(prev) : "l"(&g_bar_count), "r"(1) : "memory");
        if (prev == GRID - 1) {
            asm volatile("st.relaxed.gpu.s32 [%0], %1;" :: "l"(&g_bar_count), "r"(0) : "memory");
            asm volatile("st.release.gpu.s32 [%0], %1;" :: "l"(&g_gen), "r"(gen + 1) : "memory");
        } else {
            int cur;
            do {
                asm volatile("ld.acquire.gpu.s32 %0, [%1];" : "=r"(cur) : "l"(&g_gen) : "memory");
            } while (cur == gen);
        }
    }
    __syncthreads();
}

// ---------------- prologue: encW2 = enc @ W2^T -> fp16 ----------------
__global__ void __launch_bounds__(256) kEncW2(const float* __restrict__ enc,
                                              const float* __restrict__ attnW) {
    __shared__ float As[32][68];
    __shared__ float Bs[32][72];
    int Mblk = blockIdx.y * 64;
    int Nblk = blockIdx.x * 64;
    int tid = threadIdx.x;
    int tx = tid & 15, ty = tid >> 4;

    float2 acc[4][2];
#pragma unroll
    for (int i = 0; i < 4; i++) { acc[i][0] = make_float2(0.f, 0.f); acc[i][1] = make_float2(0.f, 0.f); }

    const float* Ag = enc + (size_t)Mblk * 512;
    const float* Bg = attnW + (size_t)Nblk * 1024 + 512;

    for (int k0 = 0; k0 < 512; k0 += 32) {
#pragma unroll
        for (int r = 0; r < 2; r++) {
            int i = r * 256 + tid;
            int m = i >> 3, g = i & 7;
            float4 v = *reinterpret_cast<const float4*>(Ag + m * 512 + k0 + g * 4);
            As[g * 4 + 0][m] = v.x; As[g * 4 + 1][m] = v.y;
            As[g * 4 + 2][m] = v.z; As[g * 4 + 3][m] = v.w;
            float4 u = *reinterpret_cast<const float4*>(Bg + m * 1024 + k0 + g * 4);
            Bs[g * 4 + 0][m] = u.x; Bs[g * 4 + 1][m] = u.y;
            Bs[g * 4 + 2][m] = u.z; Bs[g * 4 + 3][m] = u.w;
        }
        __syncthreads();
#pragma unroll
        for (int kk = 0; kk < 32; kk++) {
            float4 a4 = *reinterpret_cast<const float4*>(&As[kk][ty * 4]);
            float2 b0 = *reinterpret_cast<const float2*>(&Bs[kk][tx * 4]);
            float2 b1 = *reinterpret_cast<const float2*>(&Bs[kk][tx * 4 + 2]);
            float2 aa;
            aa.x = aa.y = a4.x; acc[0][0] = ffma2(aa, b0, acc[0][0]); acc[0][1] = ffma2(aa, b1, acc[0][1]);
            aa.x = aa.y = a4.y; acc[1][0] = ffma2(aa, b0, acc[1][0]); acc[1][1] = ffma2(aa, b1, acc[1][1]);
            aa.x = aa.y = a4.z; acc[2][0] = ffma2(aa, b0, acc[2][0]); acc[2][1] = ffma2(aa, b1, acc[2][1]);
            aa.x = aa.y = a4.w; acc[3][0] = ffma2(aa, b0, acc[3][0]); acc[3][1] = ffma2(aa, b1, acc[3][1]);
        }
        __syncthreads();
    }
#pragma unroll
    for (int i = 0; i < 4; i++) {
        __half* row = g_encW2h + (size_t)(Mblk + ty * 4 + i) * 512 + Nblk + tx * 4;
        *reinterpret_cast<__half2*>(row)     = __float22half2_rn(acc[i][0]);
        *reinterpret_cast<__half2*>(row + 2) = __float22half2_rn(acc[i][1]);
    }
}

// prologue: enc f32 -> fp16 copy
__global__ void __launch_bounds__(256) kConvEnc(const float* __restrict__ enc) {
    int stride = gridDim.x * blockDim.x;
    for (int i = blockIdx.x * blockDim.x + threadIdx.x; i < BB * SS * HH / 2; i += stride) {
        float2 v = reinterpret_cast<const float2*>(enc)[i];
        reinterpret_cast<__half2*>(g_ench)[i] = __float22half2_rn(v);
    }
}

// ================== persistent-kernel phases (blocks 0..127 work) ==================

// scores: block bi handles 32 (b,s) pairs, one batch per block; encW2 fp16 slice 32KB (L1)
__device__ __forceinline__ void scores_phase(float* sm, const float* __restrict__ v_w) {
    int bi = blockIdx.x;
    if (bi >= 128) return;
    int tid = threadIdx.x;
    int b = bi >> 3;
    float* hs = sm;  // 512: hW1 row for this batch
    hs[tid] = lcg(&g_hW1[b * HH + tid]);
    __syncthreads();
    int w = tid >> 5, l = tid & 31;
    const float2* hs2 = reinterpret_cast<const float2*>(hs);
    const float2* vw2 = reinterpret_cast<const float2*>(v_w);
#pragma unroll
    for (int it = 0; it < 2; it++) {
        int pr = bi * 32 + w * 2 + it;
        const __half2* e2 = reinterpret_cast<const __half2*>(g_encW2h + (size_t)pr * HH);
        float acc = 0.f;
#pragma unroll
        for (int i = 0; i < 8; i++) {
            int kp = l + 32 * i;
            float2 e = __half22float2(e2[kp]);
            float2 h = hs2[kp];
            float2 v = vw2[kp];
            acc += htanh(e.x + h.x) * v.x + htanh(e.y + h.y) * v.y;
        }
#pragma unroll
        for (int off = 16; off > 0; off >>= 1) acc += __shfl_xor_sync(0xffffffffu, acc, off);
        if (l == 0) g_scores[pr] = __expf(acc);
    }
}

// weighted: block = (b, 64-h chunk); enc fp16 slice 32KB (L1); scores already exp'ed
__device__ __forceinline__ void weighted_phase(float* sm) {
    int bi = blockIdx.x;
    if (bi >= 128) return;
    int tid = threadIdx.x;
    int b = bi >> 3, hc = bi & 7;
    float* wsm  = sm;                                       // 256
    float* wred = sm + 256;                                 // 8
    float2* red = reinterpret_cast<float2*>(sm + 272);      // 512 float2

    float e = (tid < 256) ? lcg(&g_scores[b * SS + tid]) : 0.f;
    if (tid < 256) wsm[tid] = e;
    float s = e;
#pragma unroll
    for (int off = 16; off > 0; off >>= 1) s += __shfl_xor_sync(0xffffffffu, s, off);
    if (tid < 256 && (tid & 31) == 0) wred[tid >> 5] = s;
    __syncthreads();
    float tot = 0.f;
#pragma unroll
    for (int i = 0; i < 8; i++) tot += wred[i];
    float inv = __fdividef(1.f, tot);

    int hp_ = tid & 31, sg = tid >> 5;   // 32 h-pairs x 16 s-groups
    float2 acc = make_float2(0.f, 0.f);
#pragma unroll
    for (int i = 0; i < 16; i++) {
        int si = sg + 16 * i;
        __half2 ev = reinterpret_cast<const __half2*>(
            g_ench + (size_t)(b * SS + si) * HH + hc * 64)[hp_];
        float2 ef = __half22float2(ev);
        float wv = wsm[si];
        acc.x += wv * ef.x; acc.y += wv * ef.y;
    }
    red[tid] = acc;
    __syncthreads();
    if (tid < 32) {
        float2 v = make_float2(0.f, 0.f);
#pragma unroll
        for (int g = 0; g < 16; g++) { float2 r = red[g * 32 + tid]; v.x += r.x; v.y += r.y; }
        v.x *= inv; v.y *= inv;
        reinterpret_cast<float2*>(g_weighted + b * HH + hc * 64)[tid] = v;
    }
}

// GRU: 128 blocks x 4 j; warp id w = bph*8 + role*4 + jrel; each warp: full K, 4 batch-pairs
template <int LAYER>
__device__ __forceinline__ void gru_phase(float* sm, int p,
                                          const float* __restrict__ Wih,
                                          const float* __restrict__ Whh,
                                          const float* __restrict__ bih,
                                          const float* __restrict__ bhh) {
    int bi = blockIdx.x;
    if (bi >= 128) return;
    int tid = threadIdx.x;
    constexpr int K = (LAYER == 0) ? KX : HH;
    float* xp = sm + OFF_XP;
    float* hp = sm + OFF_HP;
    float* ex = sm + OFF_EX;

    const float* hold = (LAYER == 0) ? g_h0[p] : g_h1[p];
    float* hnew       = (LAYER == 0) ? g_h0[1 - p] : g_h1[1 - p];

    if (LAYER == 0) {
#pragma unroll
        for (int r = 0; r < 16; r++) {
            int i = r * NTH + tid;
            int b = i >> 9, k = i & 511;
            xp[(b >> 1) * (2 * K) + 2 * k + (b & 1)] = lcg(g_weighted + b * HH + k);
        }
        if (tid < 128) {
            int b = tid >> 3, f = tid & 7;
            xp[(b >> 1) * (2 * K) + 2 * (512 + f) + (b & 1)] = lcg(g_xin + b * FF + f);
        }
    } else {
        const float* src0 = g_h0[1 - p];
#pragma unroll
        for (int r = 0; r < 16; r++) {
            int i = r * NTH + tid;
            int b = i >> 9, k = i & 511;
            xp[(b >> 1) * 1024 + 2 * k + (b & 1)] = lcg(src0 + b * HH + k);
        }
    }
#pragma unroll
    for (int r = 0; r < 16; r++) {
        int i = r * NTH + tid;
        int b = i >> 9, k = i & 511;
        hp[(b >> 1) * 1024 + 2 * k + (b & 1)] = lcg(hold + b * HH + k);
    }
    __syncthreads();

    int w = tid >> 5, l = tid & 31;
    int jrel = w & 3;
    int role = (w >> 2) & 1;   // 0 = gi, 1 = gh
    int bph  = w >> 3;         // batch-pair half: pairs bph*4 .. bph*4+3
    int j = bi * 4 + jrel;

    float2 a0[4], a1[4], a2[4];
#pragma unroll
    for (int bp = 0; bp < 4; bp++) { a0[bp] = make_float2(0.f, 0.f); a1[bp] = a0[bp]; a2[bp] = a0[bp]; }

    if (role == 0) {
        const float2* src = reinterpret_cast<const float2*>(xp) + (bph * 4) * K;
        const float* wr = Wih + (size_t)j * K + ((LAYER == 0) ? FF : 0);
        const float* wz = wr + (size_t)512 * K;
        const float* wn = wz + (size_t)512 * K;
#pragma unroll
        for (int i = 0; i < 16; i++) {
            int k = l + 32 * i;
            float r_ = wr[k], z_ = wz[k], n_ = wn[k];
            float2 rr = make_float2(r_, r_), zz = make_float2(z_, z_), nn = make_float2(n_, n_);
#pragma unroll
            for (int bp = 0; bp < 4; bp++) {
                float2 x2 = src[bp * K + k];
                a0[bp] = ffma2(x2, rr, a0[bp]);
                a1[bp] = ffma2(x2, zz, a1[bp]);
                a2[bp] = ffma2(x2, nn, a2[bp]);
            }
        }
        if (LAYER == 0 && l < FF) {
            const float* wb = Wih + (size_t)j * K;   // xin cols 0..7
            float r_ = wb[l], z_ = wb[(size_t)512 * K + l], n_ = wb[(size_t)1024 * K + l];
            float2 rr = make_float2(r_, r_), zz = make_float2(z_, z_), nn = make_float2(n_, n_);
            int k = 512 + l;
#pragma unroll
            for (int bp = 0; bp < 4; bp++) {
                float2 x2 = src[bp * K + k];
                a0[bp] = ffma2(x2, rr, a0[bp]);
                a1[bp] = ffma2(x2, zz, a1[bp]);
                a2[bp] = ffma2(x2, nn, a2[bp]);
            }
        }
    } else {
        const float2* src = reinterpret_cast<const float2*>(hp) + (bph * 4) * 512;
        const float* wr = Whh + (size_t)j * 512;
        const float* wz = wr + (size_t)512 * 512;
        const float* wn = wz + (size_t)512 * 512;
#pragma unroll
        for (int i = 0; i < 16; i++) {
            int k = l + 32 * i;
            float r_ = wr[k], z_ = wz[k], n_ = wn[k];
            float2 rr = make_float2(r_, r_), zz = make_float2(z_, z_), nn = make_float2(n_, n_);
#pragma unroll
            for (int bp = 0; bp < 4; bp++) {
                float2 x2 = src[bp * 512 + k];
                a0[bp] = ffma2(x2, rr, a0[bp]);
                a1[bp] = ffma2(x2, zz, a1[bp]);
                a2[bp] = ffma2(x2, nn, a2[bp]);
            }
        }
    }
#pragma unroll
    for (int off = 16; off > 0; off >>= 1) {
#pragma unroll
        for (int bp = 0; bp < 4; bp++) {
            a0[bp].x += __shfl_xor_sync(0xffffffffu, a0[bp].x, off);
            a0[bp].y += __shfl_xor_sync(0xffffffffu, a0[bp].y, off);
            a1[bp].x += __shfl_xor_sync(0xffffffffu, a1[bp].x, off);
            a1[bp].y += __shfl_xor_sync(0xffffffffu, a1[bp].y, off);
            a2[bp].x += __shfl_xor_sync(0xffffffffu, a2[bp].x, off);
            a2[bp].y += __shfl_xor_sync(0xffffffffu, a2[bp].y, off);
        }
    }
    if (l == 0) {
        float* dst = ex + w * 24;   // [g3][bpl4][comp2]
#pragma unroll
        for (int bp = 0; bp < 4; bp++) {
            dst[0 * 8 + bp * 2] = a0[bp].x; dst[0 * 8 + bp * 2 + 1] = a0[bp].y;
            dst[1 * 8 + bp * 2] = a1[bp].x; dst[1 * 8 + bp * 2 + 1] = a1[bp].y;
            dst[2 * 8 + bp * 2] = a2[bp].x; dst[2 * 8 + bp * 2 + 1] = a2[bp].y;
        }
    }
    __syncthreads();
    if (tid < 64) {
        int b = tid & 15, jr = tid >> 4;
        int jj = bi * 4 + jr;
        int bp = b >> 1, bph_ = bp >> 2, bpl = bp & 3, comp = b & 1;
        // writer warp id: w = bph*8 + role*4 + jrel
        const float* gi = ex + (bph_ * 8 + 0 * 4 + jr) * 24 + bpl * 2 + comp;
        const float* gh = ex + (bph_ * 8 + 1 * 4 + jr) * 24 + bpl * 2 + comp;
        float gir = gi[0], giz = gi[8], gin = gi[16];
        float ghr = gh[0], ghz = gh[8], ghn = gh[16];
        float r = hsig(gir + bih[jj] + ghr + bhh[jj]);
        float z = hsig(giz + bih[jj + 512] + ghz + bhh[jj + 512]);
        float n = htanh(gin + bih[jj + 1024] + r * (ghn + bhh[jj + 1024]));
        float hprev = hp[bp * 1024 + 2 * jj + comp];
        hnew[b * HH + jj] = (1.f - z) * n + z * hprev;
    }
}

// tail: blocks 0..127 compute 4 j of next-step hW1 (W1 slice 8KB, L1); block 128 out-proj
__device__ __forceinline__ void tail_phase(float* sm, int pn, int t,
                                           const float* __restrict__ attnW,
                                           const float* __restrict__ attnb,
                                           const float* __restrict__ outW,
                                           const float* __restrict__ outb,
                                           float* __restrict__ dout) {
    int bi = blockIdx.x;
    int tid = threadIdx.x;
    const float* h1 = g_h1[pn];

    if (bi < 128) {
        float* hp = sm + OFF_HP;
        float* ex = sm + OFF_EX;
#pragma unroll
        for (int r = 0; r < 16; r++) {
            int i = r * NTH + tid;
            int b = i >> 9, k = i & 511;
            hp[(b >> 1) * 1024 + 2 * k + (b & 1)] = lcg(h1 + b * HH + k);
        }
        __syncthreads();
        int w = tid >> 5, l = tid & 31;
        int jrel = w & 3, bph = w >> 2;   // w = bph*4 + jrel; 4 j x 4 pair-quarters (2 pairs each)
        int j = bi * 4 + jrel;
        const float2* hp2 = reinterpret_cast<const float2*>(hp) + (bph * 2) * 512;
        const float* wcol = attnW + (size_t)j * (2 * HH);   // W1 row (cols 0..511)
        float2 acc[2];
        acc[0] = make_float2(0.f, 0.f); acc[1] = acc[0];
#pragma unroll
        for (int i = 0; i < 16; i++) {
            int k = l + 32 * i;
            float wv = wcol[k];
            float2 ww = make_float2(wv, wv);
            acc[0] = ffma2(hp2[k], ww, acc[0]);
            acc[1] = ffma2(hp2[512 + k], ww, acc[1]);
        }
#pragma unroll
        for (int off = 16; off > 0; off >>= 1) {
            acc[0].x += __shfl_xor_sync(0xffffffffu, acc[0].x, off);
            acc[0].y += __shfl_xor_sync(0xffffffffu, acc[0].y, off);
            acc[1].x += __shfl_xor_sync(0xffffffffu, acc[1].x, off);
            acc[1].y += __shfl_xor_sync(0xffffffffu, acc[1].y, off);
        }
        if (l == 0) {
            float* dst = ex + w * 4;
            dst[0] = acc[0].x; dst[1] = acc[0].y; dst[2] = acc[1].x; dst[3] = acc[1].y;
        }
        __syncthreads();
        if (tid < 64) {
            int b = tid & 15, jr = tid >> 4;
            int jj = bi * 4 + jr;
            int bp = b >> 1, bph_ = bp >> 1, bpl = bp & 1, comp = b & 1;
            float v = ex[(bph_ * 4 + jr) * 4 + bpl * 2 + comp] + attnb[jj];
            g_hW1[b * HH + jj] = v;
        }
    } else if (t >= 0) {   // bi == 128: output projection + xin update
        float* red = sm + OFF_XP;
        int out = tid & 127, kc = tid >> 7;
        int b = out >> 3, f = out & 7;
        const float* wrow = outW + f * (2 * HH + FF);
        float acc = 0.f;
        if (kc < 2) {
            const float2* w2 = reinterpret_cast<const float2*>(wrow + kc * 256);
            const float* h2 = h1 + b * HH + kc * 256;
#pragma unroll
            for (int c = 0; c < 128; c++) {
                float2 wv = w2[c]; float2 hv = lcg2(h2 + 2 * c);
                acc += wv.x * hv.x + wv.y * hv.y;
            }
        } else {
            const float2* w2 = reinterpret_cast<const float2*>(wrow + 512 + (kc - 2) * 256);
            const float* g2 = g_weighted + b * HH + (kc - 2) * 256;
#pragma unroll
            for (int c = 0; c < 128; c++) {
                float2 wv = w2[c]; float2 gv = lcg2(g2 + 2 * c);
                acc += wv.x * gv.x + wv.y * gv.y;
            }
            if (kc == 3) {
#pragma unroll
                for (int c = 0; c < FF; c++) acc += wrow[2 * HH + c] * lcg(&g_xin[b * FF + c]);
                acc += outb[f];
            }
        }
        red[tid] = acc;
        __syncthreads();
        if (kc == 0) {
            float v = red[out] + red[out + 128] + red[out + 256] + red[out + 384];
            v = fmaxf(v, 0.f);
            dout[(b * TT + t) * FF + f] = v;
            g_xin[out] = v;   // next_in = out (TGT_IDX covers all F)
        }
    }
}

// ================== persistent kernel ==================
__global__ void __launch_bounds__(NTH, 1)
kPersist(const float* __restrict__ target, const float* __restrict__ hidden0,
         const float* __restrict__ attnW, const float* __restrict__ attnb,
         const float* __restrict__ v_w,
         const float* __restrict__ Wih0, const float* __restrict__ Whh0,
         const float* __restrict__ bih0, const float* __restrict__ bhh0,
         const float* __restrict__ Wih1, const float* __restrict__ Whh1,
         const float* __restrict__ bih1, const float* __restrict__ bhh1,
         const float* __restrict__ outW, const float* __restrict__ outb,
         float* __restrict__ dout)
{
    extern __shared__ float sm[];
    int tid = threadIdx.x, bi = blockIdx.x;

    for (int i = bi * NTH + tid; i < BB * HH; i += GRID * NTH) {
        g_h0[0][i] = hidden0[i];
        g_h1[0][i] = hidden0[BB * HH + i];
    }
    if (bi == 0 && tid < BB * FF) {
        int b = tid >> 3, f = tid & 7;
        g_xin[tid] = target[b * TT * FF + f];
    }
    gridbar();

    tail_phase(sm, 0, -1, attnW, attnb, outW, outb, dout);
    gridbar();

    for (int t = 0; t < TT; t++) {
        int p = t & 1, pn = 1 - p;
        scores_phase(sm, v_w);
        gridbar();
        weighted_phase(sm);
        gridbar();
        gru_phase<0>(sm, p, Wih0, Whh0, bih0, bhh0);
        gridbar();
        gru_phase<1>(sm, p, Wih1, Whh1, bih1, bhh1);
        gridbar();
        tail_phase(sm, pn, t, attnW, attnb, outW, outb, dout);
        gridbar();
    }
}

// ---------------- launch ----------------
extern "C" void kernel_launch(void* const* d_in, const int* in_sizes, int n_in,
                              void* d_out, int out_size) {
    (void)in_sizes; (void)n_in; (void)out_size;
    const float* target  = (const float*)d_in[0];
    const float* hidden0 = (const float*)d_in[1];
    const float* enc     = (const float*)d_in[2];
    const float* attnW   = (const float*)d_in[3];
    const float* attnb   = (const float*)d_in[4];
    const float* v_w     = (const float*)d_in[5];
    const float* Wih0    = (const float*)d_in[6];
    const float* Whh0    = (const float*)d_in[7];
    const float* bih0    = (const float*)d_in[8];
    const float* bhh0    = (const float*)d_in[9];
    const float* Wih1    = (const float*)d_in[10];
    const float* Whh1    = (const float*)d_in[11];
    const float* bih1    = (const float*)d_in[12];
    const float* bhh1    = (const float*)d_in[13];
    const float* outW    = (const float*)d_in[14];
    const float* outb    = (const float*)d_in[15];
    float* dout = (float*)d_out;

    const int smem = SMEM_FLOATS * 4;  // 67584 B
    static int cfg_done = 0;
    if (!cfg_done) {
        cudaFuncSetAttribute(kPersist, cudaFuncAttributeMaxDynamicSharedMemorySize, smem);
        cfg_done = 1;
    }

    kEncW2<<<dim3(8, 64), 256>>>(enc, attnW);
    kConvEnc<<<128, 256>>>(enc);
    kPersist<<<GRID, NTH, smem>>>(target, hidden0, attnW, attnb, v_w,
                                  Wih0, Whh0, bih0, bhh0,
                                  Wih1, Whh1, bih1, bhh1,
                                  outW, outb, dout);
}